// round 9
// baseline (speedup 1.0000x reference)
#include <cuda_runtime.h>
#include <cuda_bf16.h>
#include <cstdint>
#include <cmath>

// ============================================================================
// Inputs: f32 (bf16-valued, widened by harness). K=2048, R=32768.
// Output mode 0: fp32 concat [q_as_f32 (R*K) | scale (R)].
//
// R8: GEMM 734us @ tensor=61.5%, 2 warps/SMSP couldn't hide LDSM/barrier
// latency (issue=32%). This round: 512-thread CTA, tile 256x128, warp tile
// 64x32 (4 warps/SMSP), ~110 regs/thread. Same 4-stage single-barrier
// cp.async pipeline.
// ============================================================================

__device__ __nv_bfloat16 g_xb[(size_t)67108864];        // 134 MB x as bf16
__device__ __nv_bfloat16 g_ht[(size_t)2048 * 2048];     // 8 MB h^T as bf16
__device__ float        g_y[(size_t)67108864];          // 268 MB fp32 y
__device__ unsigned     g_absmax[32768];                // per-row absmax bits

static constexpr int MT = 256, NT = 128, KC = 64, STAGES = 4;
static constexpr int THREADS = 512;
static constexpr int A_STAGE_BYTES = MT * KC * 2;           // 32768
static constexpr int B_STAGE_BYTES = NT * KC * 2;           // 16384
static constexpr int SMEM_B_BASE = STAGES * A_STAGE_BYTES;  // 131072
static constexpr int SMEM_TOTAL = STAGES * (A_STAGE_BYTES + B_STAGE_BYTES); // 196608

__device__ __forceinline__ uint32_t smem_u32(const void* p) {
    uint32_t a;
    asm("{ .reg .u64 t; cvta.to.shared.u64 t, %1; cvt.u32.u64 %0, t; }"
        : "=r"(a) : "l"(p));
    return a;
}
__device__ __forceinline__ uint32_t swz(uint32_t off) {
    return off ^ ((off >> 3) & 0x70u);
}
__device__ __forceinline__ void cp_async16(uint32_t s_addr, const void* g_addr) {
    asm volatile("cp.async.cg.shared.global [%0], [%1], 16;"
                 :: "r"(s_addr), "l"(g_addr) : "memory");
}
#define CP_COMMIT() asm volatile("cp.async.commit_group;" ::: "memory")
#define CP_WAIT(n)  asm volatile("cp.async.wait_group %0;" :: "n"(n) : "memory")

__device__ __forceinline__ void ldmatrix_x4(uint32_t* r, uint32_t addr) {
    asm volatile("ldmatrix.sync.aligned.m8n8.x4.shared.b16 {%0,%1,%2,%3}, [%4];"
                 : "=r"(r[0]), "=r"(r[1]), "=r"(r[2]), "=r"(r[3]) : "r"(addr));
}
__device__ __forceinline__ void mma_16816(float* d, const uint32_t* a,
                                          uint32_t b0, uint32_t b1) {
    asm volatile(
        "mma.sync.aligned.m16n8k16.row.col.f32.bf16.bf16.f32 "
        "{%0,%1,%2,%3}, {%4,%5,%6,%7}, {%8,%9}, {%0,%1,%2,%3};"
        : "+f"(d[0]), "+f"(d[1]), "+f"(d[2]), "+f"(d[3])
        : "r"(a[0]), "r"(a[1]), "r"(a[2]), "r"(a[3]), "r"(b0), "r"(b1));
}

__global__ void zero_absmax_kernel(int R) {
    int i = blockIdx.x * blockDim.x + threadIdx.x;
    if (i < R) g_absmax[i] = 0u;
}

__global__ void __launch_bounds__(256) convert_x_kernel(
    const float4* __restrict__ xf, long long n4) {
    long long i = (long long)blockIdx.x * blockDim.x + threadIdx.x;
    long long base = i * 2;
    if (base + 1 < n4) {
        float4 v0 = xf[base + 0];
        float4 v1 = xf[base + 1];
        __nv_bfloat16 o[8] = {
            __float2bfloat16(v0.x), __float2bfloat16(v0.y),
            __float2bfloat16(v0.z), __float2bfloat16(v0.w),
            __float2bfloat16(v1.x), __float2bfloat16(v1.y),
            __float2bfloat16(v1.z), __float2bfloat16(v1.w)};
        *reinterpret_cast<uint4*>(&g_xb[base * 4]) =
            *reinterpret_cast<const uint4*>(o);
    }
}

__global__ void transpose_h_kernel(const float* __restrict__ h, int K) {
    __shared__ float tile[32][33];
    int x = blockIdx.x * 32 + threadIdx.x;
    int y = blockIdx.y * 32 + threadIdx.y;
#pragma unroll
    for (int j = 0; j < 32; j += 8)
        tile[threadIdx.y + j][threadIdx.x] = h[(size_t)(y + j) * K + x];
    __syncthreads();
    int xo = blockIdx.y * 32 + threadIdx.x;
    int yo = blockIdx.x * 32 + threadIdx.y;
#pragma unroll
    for (int j = 0; j < 32; j += 8)
        g_ht[(size_t)(yo + j) * K + xo] =
            __float2bfloat16(tile[threadIdx.x][threadIdx.y + j]);
}

// ============================================================================
// GEMM + fused row absmax. 16 warps = 4(M) x 4(N), warp tile 64x32.
// ============================================================================
__device__ __forceinline__ void load_stage(uint32_t sA, uint32_t sB,
                                           const __nv_bfloat16* a_src,
                                           const __nv_bfloat16* b_src,
                                           int tid, int K) {
    // A: 256 rows x 8 chunks(16B) = 2048 chunks, 4 per thread
#pragma unroll
    for (int i = 0; i < 4; i++) {
        int idx = tid + i * THREADS;
        int row = idx >> 3, c = idx & 7;
        uint32_t off = swz((uint32_t)row * 128u + (uint32_t)c * 16u);
        cp_async16(sA + off, a_src + (size_t)row * K + c * 8);
    }
    // B: 128 rows x 8 chunks = 1024 chunks, 2 per thread
#pragma unroll
    for (int i = 0; i < 2; i++) {
        int idx = tid + i * THREADS;
        int row = idx >> 3, c = idx & 7;
        uint32_t off = swz((uint32_t)row * 128u + (uint32_t)c * 16u);
        cp_async16(sB + off, b_src + (size_t)row * K + c * 8);
    }
}

__global__ void __launch_bounds__(THREADS, 1) gemm_absmax_kernel(int K) {
    extern __shared__ char smem[];
    const uint32_t smem_base = smem_u32(smem);
    const int tid = threadIdx.x;
    const int wid = tid >> 5;
    const int lane = tid & 31;
    const int wm = wid >> 2;    // 0..3 (M)
    const int wn = wid & 3;     // 0..3 (N)

    const int m0 = blockIdx.y * MT;
    const int n0 = blockIdx.x * NT;
    const __nv_bfloat16* Ag = g_xb + (size_t)m0 * K;
    const __nv_bfloat16* Bg = g_ht + (size_t)n0 * K;

    float d[4][4][4];   // [m16 tile][n8 tile][frag]
#pragma unroll
    for (int mi = 0; mi < 4; mi++)
#pragma unroll
        for (int ni = 0; ni < 4; ni++)
#pragma unroll
            for (int j = 0; j < 4; j++) d[mi][ni][j] = 0.0f;

#pragma unroll
    for (int s = 0; s < STAGES - 1; s++) {
        load_stage(smem_base + s * A_STAGE_BYTES,
                   smem_base + SMEM_B_BASE + s * B_STAGE_BYTES,
                   Ag + s * KC, Bg + s * KC, tid, K);
        CP_COMMIT();
    }

    const int lrow = lane & 15;
    const int lkb  = (lane >> 4) * 8;
    const int NCHUNK = K / KC;   // 32

    for (int kc = 0; kc < NCHUNK; kc++) {
        CP_WAIT(STAGES - 2);
        // Single barrier: arrived stage visible AND write-target stage
        // (= (kc-1)%S, whose compute just finished) drained by all warps.
        __syncthreads();

        int knext = kc + STAGES - 1;
        if (knext < NCHUNK) {
            int s = knext % STAGES;
            load_stage(smem_base + s * A_STAGE_BYTES,
                       smem_base + SMEM_B_BASE + s * B_STAGE_BYTES,
                       Ag + knext * KC, Bg + knext * KC, tid, K);
        }
        CP_COMMIT();

        const int st = kc % STAGES;
        const uint32_t sA = smem_base + st * A_STAGE_BYTES;
        const uint32_t sB = smem_base + SMEM_B_BASE + st * B_STAGE_BYTES;

#pragma unroll
        for (int s = 0; s < KC / 16; s++) {
            uint32_t a[4][4], b[2][4];
#pragma unroll
            for (int mi = 0; mi < 4; mi++) {
                int row = wm * 64 + mi * 16 + lrow;
                uint32_t off = swz((uint32_t)row * 128u +
                                   (uint32_t)(s * 16 + lkb) * 2u);
                ldmatrix_x4(a[mi], sA + off);
            }
#pragma unroll
            for (int nj = 0; nj < 2; nj++) {
                int row = wn * 32 + nj * 16 + lrow;
                uint32_t off = swz((uint32_t)row * 128u +
                                   (uint32_t)(s * 16 + lkb) * 2u);
                ldmatrix_x4(b[nj], sB + off);
            }
#pragma unroll
            for (int mi = 0; mi < 4; mi++)
#pragma unroll
                for (int nj = 0; nj < 2; nj++) {
                    mma_16816(d[mi][2 * nj + 0], a[mi], b[nj][0], b[nj][2]);
                    mma_16816(d[mi][2 * nj + 1], a[mi], b[nj][1], b[nj][3]);
                }
        }
    }

    // epilogue: fp32 y + per-row absmax (4-lane shfl reduce + atomicMax)
    const int g = lane >> 2;
    const int tc = (lane & 3) * 2;
#pragma unroll
    for (int mi = 0; mi < 4; mi++) {
#pragma unroll
        for (int half = 0; half < 2; half++) {
            int r = m0 + wm * 64 + mi * 16 + half * 8 + g;
            float* yrow = g_y + (size_t)r * K + n0 + wn * 32;
            float mx = 0.0f;
#pragma unroll
            for (int ni = 0; ni < 4; ni++) {
                float v0 = d[mi][ni][half * 2 + 0];
                float v1 = d[mi][ni][half * 2 + 1];
                mx = fmaxf(mx, fmaxf(fabsf(v0), fabsf(v1)));
                *reinterpret_cast<float2*>(yrow + ni * 8 + tc) =
                    make_float2(v0, v1);
            }
            mx = fmaxf(mx, __shfl_xor_sync(0xFFFFFFFFu, mx, 1));
            mx = fmaxf(mx, __shfl_xor_sync(0xFFFFFFFFu, mx, 2));
            if ((lane & 3) == 0)
                atomicMax(&g_absmax[r], __float_as_uint(mx));
        }
    }
}

// ============================================================================
// quantize. mode 0 = fp32 concat [q_as_f32 | scale].
// ============================================================================
__global__ void __launch_bounds__(256) quant_kernel(void* __restrict__ d_out,
                                                    int K, long long R, int mode) {
    const int r = blockIdx.x;
    const int tid = threadIdx.x;
    const float amax = __uint_as_float(g_absmax[r]);
    const float scale = amax / 127.0f;
    const float safe = (scale == 0.0f) ? 1.0f : scale;
    const float inv = 1.0f / safe;

    const float4* yrow = reinterpret_cast<const float4*>(g_y + (size_t)r * K);
    const long long qelems = R * (long long)K;

    for (int i = tid; i < K / 4; i += 256) {
        float4 v = yrow[i];
        float vals[4] = {v.x, v.y, v.z, v.w};
        float q[4];
#pragma unroll
        for (int j = 0; j < 4; j++) {
            float t = rintf(vals[j] * inv);
            q[j] = fminf(fmaxf(t, -127.0f), 127.0f);
        }
        if (mode == 0) {
            float* out = reinterpret_cast<float*>(d_out) + (size_t)r * K + i * 4;
            *reinterpret_cast<float4*>(out) = make_float4(q[0], q[1], q[2], q[3]);
        } else {
            uint32_t p = (uint32_t)((int)q[0] & 0xFF) |
                         ((uint32_t)((int)q[1] & 0xFF) << 8) |
                         ((uint32_t)((int)q[2] & 0xFF) << 16) |
                         ((uint32_t)((int)q[3] & 0xFF) << 24);
            reinterpret_cast<uint32_t*>(
                reinterpret_cast<char*>(d_out) + (size_t)r * K)[i] = p;
        }
    }
    if (tid == 0) {
        if (mode == 0) {
            reinterpret_cast<float*>(d_out)[qelems + r] = scale;
        } else if (mode == 1) {
            float* sc = reinterpret_cast<float*>(
                reinterpret_cast<char*>(d_out) + qelems);
            sc[r] = scale;
        }
    }
}

// ============================================================================
// launcher (graph-capture clean)
// ============================================================================
static int isqrt_ll(long long v) {
    long long r = (long long)sqrt((double)v);
    while (r * r > v) r--;
    while ((r + 1) * (r + 1) <= v) r++;
    return (int)r;
}

extern "C" void kernel_launch(void* const* d_in, const int* in_sizes, int n_in,
                              void* d_out, int out_size) {
    long long s0 = in_sizes[0], s1 = (n_in > 1) ? in_sizes[1] : 0;
    const void* xv; const void* hv;
    long long numel_x, numel_h;
    if (s0 >= s1) { xv = d_in[0]; numel_x = s0; hv = d_in[1]; numel_h = s1; }
    else          { xv = d_in[1]; numel_x = s1; hv = d_in[0]; numel_h = s0; }
    const int K = isqrt_ll(numel_h);        // 2048
    const long long R = numel_x / K;        // 32768
    const long long qelems = R * (long long)K;

    int mode;
    if ((long long)out_size == qelems + R)            mode = 0;
    else if ((long long)out_size == qelems + 4LL * R) mode = 1;
    else                                              mode = 2;

    cudaFuncSetAttribute(gemm_absmax_kernel,
                         cudaFuncAttributeMaxDynamicSharedMemorySize, SMEM_TOTAL);

    zero_absmax_kernel<<<(unsigned)((R + 255) / 256), 256>>>((int)R);
    convert_x_kernel<<<(unsigned)((numel_x / 8 + 255) / 256), 256>>>(
        (const float4*)xv, numel_x / 4);
    transpose_h_kernel<<<dim3(K / 32, K / 32), dim3(32, 8)>>>((const float*)hv, K);
    gemm_absmax_kernel<<<dim3(K / NT, (unsigned)(R / MT)), THREADS, SMEM_TOTAL>>>(K);
    quant_kernel<<<(unsigned)R, 256>>>(d_out, K, R, mode);
}

// round 10
// speedup vs baseline: 1.0405x; 1.0405x over previous
#include <cuda_runtime.h>
#include <cuda_bf16.h>
#include <cstdint>
#include <cmath>

// ============================================================================
// Inputs: f32 (bf16-valued, widened by harness). K=2048, R=32768.
// Output mode 0: fp32 concat [q_as_f32 (R*K) | scale (R)].
//
// R9 regressed: warp tile 64x32 halved MMA/LDSM ratio -> L1 50.9% bound.
// R10: warp tile back to 64x64 (MMA/LDSM=4.0), CTA 128x128 with 4 warps,
// 3-stage x 32KB smem = 96KB -> 2 CTAs/SM for cross-CTA barrier overlap.
// ============================================================================

__device__ __nv_bfloat16 g_xb[(size_t)67108864];        // 134 MB x as bf16
__device__ __nv_bfloat16 g_ht[(size_t)2048 * 2048];     // 8 MB h^T as bf16
__device__ float        g_y[(size_t)67108864];          // 268 MB fp32 y
__device__ unsigned     g_absmax[32768];                // per-row absmax bits

static constexpr int MT = 128, NT = 128, KC = 64, STAGES = 3;
static constexpr int THREADS = 128;
static constexpr int A_STAGE_BYTES = MT * KC * 2;           // 16384
static constexpr int B_STAGE_BYTES = NT * KC * 2;           // 16384
static constexpr int SMEM_B_BASE = STAGES * A_STAGE_BYTES;  // 49152
static constexpr int SMEM_TOTAL = STAGES * (A_STAGE_BYTES + B_STAGE_BYTES); // 98304

__device__ __forceinline__ uint32_t smem_u32(const void* p) {
    uint32_t a;
    asm("{ .reg .u64 t; cvta.to.shared.u64 t, %1; cvt.u32.u64 %0, t; }"
        : "=r"(a) : "l"(p));
    return a;
}
__device__ __forceinline__ uint32_t swz(uint32_t off) {
    return off ^ ((off >> 3) & 0x70u);
}
__device__ __forceinline__ void cp_async16(uint32_t s_addr, const void* g_addr) {
    asm volatile("cp.async.cg.shared.global [%0], [%1], 16;"
                 :: "r"(s_addr), "l"(g_addr) : "memory");
}
#define CP_COMMIT() asm volatile("cp.async.commit_group;" ::: "memory")
#define CP_WAIT(n)  asm volatile("cp.async.wait_group %0;" :: "n"(n) : "memory")

__device__ __forceinline__ void ldmatrix_x4(uint32_t* r, uint32_t addr) {
    asm volatile("ldmatrix.sync.aligned.m8n8.x4.shared.b16 {%0,%1,%2,%3}, [%4];"
                 : "=r"(r[0]), "=r"(r[1]), "=r"(r[2]), "=r"(r[3]) : "r"(addr));
}
__device__ __forceinline__ void mma_16816(float* d, const uint32_t* a,
                                          uint32_t b0, uint32_t b1) {
    asm volatile(
        "mma.sync.aligned.m16n8k16.row.col.f32.bf16.bf16.f32 "
        "{%0,%1,%2,%3}, {%4,%5,%6,%7}, {%8,%9}, {%0,%1,%2,%3};"
        : "+f"(d[0]), "+f"(d[1]), "+f"(d[2]), "+f"(d[3])
        : "r"(a[0]), "r"(a[1]), "r"(a[2]), "r"(a[3]), "r"(b0), "r"(b1));
}

__global__ void zero_absmax_kernel(int R) {
    int i = blockIdx.x * blockDim.x + threadIdx.x;
    if (i < R) g_absmax[i] = 0u;
}

__global__ void __launch_bounds__(256) convert_x_kernel(
    const float4* __restrict__ xf, long long n4) {
    long long i = (long long)blockIdx.x * blockDim.x + threadIdx.x;
    long long base = i * 2;
    if (base + 1 < n4) {
        float4 v0 = xf[base + 0];
        float4 v1 = xf[base + 1];
        __nv_bfloat16 o[8] = {
            __float2bfloat16(v0.x), __float2bfloat16(v0.y),
            __float2bfloat16(v0.z), __float2bfloat16(v0.w),
            __float2bfloat16(v1.x), __float2bfloat16(v1.y),
            __float2bfloat16(v1.z), __float2bfloat16(v1.w)};
        *reinterpret_cast<uint4*>(&g_xb[base * 4]) =
            *reinterpret_cast<const uint4*>(o);
    }
}

__global__ void transpose_h_kernel(const float* __restrict__ h, int K) {
    __shared__ float tile[32][33];
    int x = blockIdx.x * 32 + threadIdx.x;
    int y = blockIdx.y * 32 + threadIdx.y;
#pragma unroll
    for (int j = 0; j < 32; j += 8)
        tile[threadIdx.y + j][threadIdx.x] = h[(size_t)(y + j) * K + x];
    __syncthreads();
    int xo = blockIdx.y * 32 + threadIdx.x;
    int yo = blockIdx.x * 32 + threadIdx.y;
#pragma unroll
    for (int j = 0; j < 32; j += 8)
        g_ht[(size_t)(yo + j) * K + xo] =
            __float2bfloat16(tile[threadIdx.x][threadIdx.y + j]);
}

// ============================================================================
// GEMM + fused row absmax. 4 warps = 2(M) x 2(N), warp tile 64x64.
// 3-stage cp.async pipeline, single barrier per K-iteration, 2 CTAs/SM.
// ============================================================================
__device__ __forceinline__ void load_stage(uint32_t sA, uint32_t sB,
                                           const __nv_bfloat16* a_src,
                                           const __nv_bfloat16* b_src,
                                           int tid, int K) {
    // A: 128 rows x 8 chunks(16B) = 1024 chunks, 8 per thread
#pragma unroll
    for (int i = 0; i < 8; i++) {
        int idx = tid + i * THREADS;
        int row = idx >> 3, c = idx & 7;
        uint32_t off = swz((uint32_t)row * 128u + (uint32_t)c * 16u);
        cp_async16(sA + off, a_src + (size_t)row * K + c * 8);
    }
    // B: 128 rows x 8 chunks = 1024 chunks, 8 per thread
#pragma unroll
    for (int i = 0; i < 8; i++) {
        int idx = tid + i * THREADS;
        int row = idx >> 3, c = idx & 7;
        uint32_t off = swz((uint32_t)row * 128u + (uint32_t)c * 16u);
        cp_async16(sB + off, b_src + (size_t)row * K + c * 8);
    }
}

__global__ void __launch_bounds__(THREADS, 2) gemm_absmax_kernel(int K) {
    extern __shared__ char smem[];
    const uint32_t smem_base = smem_u32(smem);
    const int tid = threadIdx.x;
    const int wid = tid >> 5;
    const int lane = tid & 31;
    const int wm = wid >> 1;    // 0..1 (M)
    const int wn = wid & 1;     // 0..1 (N)

    const int m0 = blockIdx.y * MT;
    const int n0 = blockIdx.x * NT;
    const __nv_bfloat16* Ag = g_xb + (size_t)m0 * K;
    const __nv_bfloat16* Bg = g_ht + (size_t)n0 * K;

    float d[4][8][4];   // [m16][n8][frag]
#pragma unroll
    for (int mi = 0; mi < 4; mi++)
#pragma unroll
        for (int ni = 0; ni < 8; ni++)
#pragma unroll
            for (int j = 0; j < 4; j++) d[mi][ni][j] = 0.0f;

#pragma unroll
    for (int s = 0; s < STAGES - 1; s++) {
        load_stage(smem_base + s * A_STAGE_BYTES,
                   smem_base + SMEM_B_BASE + s * B_STAGE_BYTES,
                   Ag + s * KC, Bg + s * KC, tid, K);
        CP_COMMIT();
    }

    const int lrow = lane & 15;
    const int lkb  = (lane >> 4) * 8;
    const int NCHUNK = K / KC;   // 32

    for (int kc = 0; kc < NCHUNK; kc++) {
        CP_WAIT(STAGES - 2);
        __syncthreads();   // arrived stage visible + write-target drained

        int knext = kc + STAGES - 1;
        if (knext < NCHUNK) {
            int s = knext % STAGES;
            load_stage(smem_base + s * A_STAGE_BYTES,
                       smem_base + SMEM_B_BASE + s * B_STAGE_BYTES,
                       Ag + knext * KC, Bg + knext * KC, tid, K);
        }
        CP_COMMIT();

        const int st = kc % STAGES;
        const uint32_t sA = smem_base + st * A_STAGE_BYTES;
        const uint32_t sB = smem_base + SMEM_B_BASE + st * B_STAGE_BYTES;

#pragma unroll
        for (int s = 0; s < KC / 16; s++) {
            uint32_t a[4][4], b[4][4];
#pragma unroll
            for (int mi = 0; mi < 4; mi++) {
                int row = wm * 64 + mi * 16 + lrow;
                uint32_t off = swz((uint32_t)row * 128u +
                                   (uint32_t)(s * 16 + lkb) * 2u);
                ldmatrix_x4(a[mi], sA + off);
            }
#pragma unroll
            for (int nj = 0; nj < 4; nj++) {
                int row = wn * 64 + nj * 16 + lrow;
                uint32_t off = swz((uint32_t)row * 128u +
                                   (uint32_t)(s * 16 + lkb) * 2u);
                ldmatrix_x4(b[nj], sB + off);
            }
#pragma unroll
            for (int mi = 0; mi < 4; mi++)
#pragma unroll
                for (int nj = 0; nj < 4; nj++) {
                    mma_16816(d[mi][2 * nj + 0], a[mi], b[nj][0], b[nj][2]);
                    mma_16816(d[mi][2 * nj + 1], a[mi], b[nj][1], b[nj][3]);
                }
        }
    }

    // epilogue: fp32 y + per-row absmax (4-lane shfl reduce + atomicMax)
    const int g = lane >> 2;
    const int tc = (lane & 3) * 2;
#pragma unroll
    for (int mi = 0; mi < 4; mi++) {
#pragma unroll
        for (int half = 0; half < 2; half++) {
            int r = m0 + wm * 64 + mi * 16 + half * 8 + g;
            float* yrow = g_y + (size_t)r * K + n0 + wn * 64;
            float mx = 0.0f;
#pragma unroll
            for (int ni = 0; ni < 8; ni++) {
                float v0 = d[mi][ni][half * 2 + 0];
                float v1 = d[mi][ni][half * 2 + 1];
                mx = fmaxf(mx, fmaxf(fabsf(v0), fabsf(v1)));
                *reinterpret_cast<float2*>(yrow + ni * 8 + tc) =
                    make_float2(v0, v1);
            }
            mx = fmaxf(mx, __shfl_xor_sync(0xFFFFFFFFu, mx, 1));
            mx = fmaxf(mx, __shfl_xor_sync(0xFFFFFFFFu, mx, 2));
            if ((lane & 3) == 0)
                atomicMax(&g_absmax[r], __float_as_uint(mx));
        }
    }
}

// ============================================================================
// quantize. mode 0 = fp32 concat [q_as_f32 | scale].
// ============================================================================
__global__ void __launch_bounds__(256) quant_kernel(void* __restrict__ d_out,
                                                    int K, long long R, int mode) {
    const int r = blockIdx.x;
    const int tid = threadIdx.x;
    const float amax = __uint_as_float(g_absmax[r]);
    const float scale = amax / 127.0f;
    const float safe = (scale == 0.0f) ? 1.0f : scale;
    const float inv = 1.0f / safe;

    const float4* yrow = reinterpret_cast<const float4*>(g_y + (size_t)r * K);
    const long long qelems = R * (long long)K;

    for (int i = tid; i < K / 4; i += 256) {
        float4 v = yrow[i];
        float vals[4] = {v.x, v.y, v.z, v.w};
        float q[4];
#pragma unroll
        for (int j = 0; j < 4; j++) {
            float t = rintf(vals[j] * inv);
            q[j] = fminf(fmaxf(t, -127.0f), 127.0f);
        }
        if (mode == 0) {
            float* out = reinterpret_cast<float*>(d_out) + (size_t)r * K + i * 4;
            *reinterpret_cast<float4*>(out) = make_float4(q[0], q[1], q[2], q[3]);
        } else {
            uint32_t p = (uint32_t)((int)q[0] & 0xFF) |
                         ((uint32_t)((int)q[1] & 0xFF) << 8) |
                         ((uint32_t)((int)q[2] & 0xFF) << 16) |
                         ((uint32_t)((int)q[3] & 0xFF) << 24);
            reinterpret_cast<uint32_t*>(
                reinterpret_cast<char*>(d_out) + (size_t)r * K)[i] = p;
        }
    }
    if (tid == 0) {
        if (mode == 0) {
            reinterpret_cast<float*>(d_out)[qelems + r] = scale;
        } else if (mode == 1) {
            float* sc = reinterpret_cast<float*>(
                reinterpret_cast<char*>(d_out) + qelems);
            sc[r] = scale;
        }
    }
}

// ============================================================================
// launcher (graph-capture clean)
// ============================================================================
static int isqrt_ll(long long v) {
    long long r = (long long)sqrt((double)v);
    while (r * r > v) r--;
    while ((r + 1) * (r + 1) <= v) r++;
    return (int)r;
}

extern "C" void kernel_launch(void* const* d_in, const int* in_sizes, int n_in,
                              void* d_out, int out_size) {
    long long s0 = in_sizes[0], s1 = (n_in > 1) ? in_sizes[1] : 0;
    const void* xv; const void* hv;
    long long numel_x, numel_h;
    if (s0 >= s1) { xv = d_in[0]; numel_x = s0; hv = d_in[1]; numel_h = s1; }
    else          { xv = d_in[1]; numel_x = s1; hv = d_in[0]; numel_h = s0; }
    const int K = isqrt_ll(numel_h);        // 2048
    const long long R = numel_x / K;        // 32768
    const long long qelems = R * (long long)K;

    int mode;
    if ((long long)out_size == qelems + R)            mode = 0;
    else if ((long long)out_size == qelems + 4LL * R) mode = 1;
    else                                              mode = 2;

    cudaFuncSetAttribute(gemm_absmax_kernel,
                         cudaFuncAttributeMaxDynamicSharedMemorySize, SMEM_TOTAL);

    zero_absmax_kernel<<<(unsigned)((R + 255) / 256), 256>>>((int)R);
    convert_x_kernel<<<(unsigned)((numel_x / 8 + 255) / 256), 256>>>(
        (const float4*)xv, numel_x / 4);
    transpose_h_kernel<<<dim3(K / 32, K / 32), dim3(32, 8)>>>((const float*)hv, K);
    gemm_absmax_kernel<<<dim3(K / NT, (unsigned)(R / MT)), THREADS, SMEM_TOTAL>>>(K);
    quant_kernel<<<(unsigned)R, 256>>>(d_out, K, R, mode);
}

// round 11
// speedup vs baseline: 1.0618x; 1.0205x over previous
#include <cuda_runtime.h>
#include <cuda_bf16.h>
#include <cstdint>
#include <cmath>

// ============================================================================
// Inputs: f32 (bf16-valued, widened by harness). K=2048, R=32768.
// Output mode 0: fp32 concat [q_as_f32 (R*K) | scale (R)].
//
// R10: 726us GEMM @ tensor=62.5%, 2 CTAs/SM. Chunk-head cp.async burst (16
// deep + IMADs) contends with first LDSMs on the LSU -> MMA starvation.
// R11: spread cp.asyncs 4-per-k-step BETWEEN ldsm and mma of each step;
// first LDSM group issues immediately after the barrier.
// ============================================================================

__device__ __nv_bfloat16 g_xb[(size_t)67108864];        // 134 MB x as bf16
__device__ __nv_bfloat16 g_ht[(size_t)2048 * 2048];     // 8 MB h^T as bf16
__device__ float        g_y[(size_t)67108864];          // 268 MB fp32 y
__device__ unsigned     g_absmax[32768];                // per-row absmax bits

static constexpr int MT = 128, NT = 128, KC = 64, STAGES = 3;
static constexpr int THREADS = 128;
static constexpr int A_STAGE_BYTES = MT * KC * 2;           // 16384
static constexpr int B_STAGE_BYTES = NT * KC * 2;           // 16384
static constexpr int SMEM_B_BASE = STAGES * A_STAGE_BYTES;  // 49152
static constexpr int SMEM_TOTAL = STAGES * (A_STAGE_BYTES + B_STAGE_BYTES); // 98304

__device__ __forceinline__ uint32_t smem_u32(const void* p) {
    uint32_t a;
    asm("{ .reg .u64 t; cvta.to.shared.u64 t, %1; cvt.u32.u64 %0, t; }"
        : "=r"(a) : "l"(p));
    return a;
}
__device__ __forceinline__ uint32_t swz(uint32_t off) {
    return off ^ ((off >> 3) & 0x70u);
}
__device__ __forceinline__ void cp_async16(uint32_t s_addr, const void* g_addr) {
    asm volatile("cp.async.cg.shared.global [%0], [%1], 16;"
                 :: "r"(s_addr), "l"(g_addr) : "memory");
}
#define CP_COMMIT() asm volatile("cp.async.commit_group;" ::: "memory")
#define CP_WAIT(n)  asm volatile("cp.async.wait_group %0;" :: "n"(n) : "memory")

__device__ __forceinline__ void ldmatrix_x4(uint32_t* r, uint32_t addr) {
    asm volatile("ldmatrix.sync.aligned.m8n8.x4.shared.b16 {%0,%1,%2,%3}, [%4];"
                 : "=r"(r[0]), "=r"(r[1]), "=r"(r[2]), "=r"(r[3]) : "r"(addr));
}
__device__ __forceinline__ void mma_16816(float* d, const uint32_t* a,
                                          uint32_t b0, uint32_t b1) {
    asm volatile(
        "mma.sync.aligned.m16n8k16.row.col.f32.bf16.bf16.f32 "
        "{%0,%1,%2,%3}, {%4,%5,%6,%7}, {%8,%9}, {%0,%1,%2,%3};"
        : "+f"(d[0]), "+f"(d[1]), "+f"(d[2]), "+f"(d[3])
        : "r"(a[0]), "r"(a[1]), "r"(a[2]), "r"(a[3]), "r"(b0), "r"(b1));
}

__global__ void zero_absmax_kernel(int R) {
    int i = blockIdx.x * blockDim.x + threadIdx.x;
    if (i < R) g_absmax[i] = 0u;
}

__global__ void __launch_bounds__(256) convert_x_kernel(
    const float4* __restrict__ xf, long long n4) {
    long long i = (long long)blockIdx.x * blockDim.x + threadIdx.x;
    long long base = i * 2;
    if (base + 1 < n4) {
        float4 v0 = xf[base + 0];
        float4 v1 = xf[base + 1];
        __nv_bfloat16 o[8] = {
            __float2bfloat16(v0.x), __float2bfloat16(v0.y),
            __float2bfloat16(v0.z), __float2bfloat16(v0.w),
            __float2bfloat16(v1.x), __float2bfloat16(v1.y),
            __float2bfloat16(v1.z), __float2bfloat16(v1.w)};
        *reinterpret_cast<uint4*>(&g_xb[base * 4]) =
            *reinterpret_cast<const uint4*>(o);
    }
}

__global__ void transpose_h_kernel(const float* __restrict__ h, int K) {
    __shared__ float tile[32][33];
    int x = blockIdx.x * 32 + threadIdx.x;
    int y = blockIdx.y * 32 + threadIdx.y;
#pragma unroll
    for (int j = 0; j < 32; j += 8)
        tile[threadIdx.y + j][threadIdx.x] = h[(size_t)(y + j) * K + x];
    __syncthreads();
    int xo = blockIdx.y * 32 + threadIdx.x;
    int yo = blockIdx.x * 32 + threadIdx.y;
#pragma unroll
    for (int j = 0; j < 32; j += 8)
        g_ht[(size_t)(yo + j) * K + xo] =
            __float2bfloat16(tile[threadIdx.x][threadIdx.y + j]);
}

// ============================================================================
// GEMM + fused row absmax. 4 warps = 2(M) x 2(N), warp tile 64x64.
// 3-stage pipeline, 2 CTAs/SM, cp.asyncs interleaved into k-steps.
// ============================================================================
__global__ void __launch_bounds__(THREADS, 2) gemm_absmax_kernel(int K) {
    extern __shared__ char smem[];
    const uint32_t smem_base = smem_u32(smem);
    const int tid = threadIdx.x;
    const int wid = tid >> 5;
    const int lane = tid & 31;
    const int wm = wid >> 1;    // 0..1 (M)
    const int wn = wid & 1;     // 0..1 (N)

    const int m0 = blockIdx.y * MT;
    const int n0 = blockIdx.x * NT;
    const __nv_bfloat16* Ag = g_xb + (size_t)m0 * K;
    const __nv_bfloat16* Bg = g_ht + (size_t)n0 * K;

    // per-thread load slot: 16 chunks of 16B (8 A, 8 B), same smem offset
    // within every stage; global ptr advances by KC per chunk.
    const int lrow0 = tid >> 3;         // 0..15
    const int lcol  = tid & 7;          // 0..7
    uint32_t ld_soff[16];
    const __nv_bfloat16* ld_gptr[16];
#pragma unroll
    for (int i = 0; i < 8; i++) {       // A rows lrow0 + i*16
        int row = lrow0 + i * 16;
        ld_soff[i] = swz((uint32_t)row * 128u + (uint32_t)lcol * 16u);
        ld_gptr[i] = Ag + (size_t)row * K + lcol * 8;
    }
#pragma unroll
    for (int i = 0; i < 8; i++) {       // B rows lrow0 + i*16
        int row = lrow0 + i * 16;
        ld_soff[8 + i] = swz((uint32_t)row * 128u + (uint32_t)lcol * 16u);
        ld_gptr[8 + i] = Bg + (size_t)row * K + lcol * 8;
    }

    float d[4][8][4];
#pragma unroll
    for (int mi = 0; mi < 4; mi++)
#pragma unroll
        for (int ni = 0; ni < 8; ni++)
#pragma unroll
            for (int j = 0; j < 4; j++) d[mi][ni][j] = 0.0f;

    // prologue: stages 0..1
#pragma unroll
    for (int s = 0; s < STAGES - 1; s++) {
        uint32_t sA = smem_base + s * A_STAGE_BYTES;
        uint32_t sB = smem_base + SMEM_B_BASE + s * B_STAGE_BYTES;
#pragma unroll
        for (int i = 0; i < 8; i++)  cp_async16(sA + ld_soff[i], ld_gptr[i]);
#pragma unroll
        for (int i = 0; i < 8; i++)  cp_async16(sB + ld_soff[8 + i], ld_gptr[8 + i]);
        CP_COMMIT();
#pragma unroll
        for (int i = 0; i < 16; i++) ld_gptr[i] += KC;
    }

    const int lrow = lane & 15;
    const int lkb  = (lane >> 4) * 8;
    const int NCHUNK = K / KC;   // 32

    for (int kc = 0; kc < NCHUNK; kc++) {
        CP_WAIT(STAGES - 2);
        __syncthreads();   // arrived stage visible + write-target drained

        const bool do_load = (kc + STAGES - 1) < NCHUNK;
        const int wst = (kc + STAGES - 1) % STAGES;   // write stage
        const uint32_t wA = smem_base + wst * A_STAGE_BYTES;
        const uint32_t wB = smem_base + SMEM_B_BASE + wst * B_STAGE_BYTES;

        const int st = kc % STAGES;
        const uint32_t sA = smem_base + st * A_STAGE_BYTES;
        const uint32_t sB = smem_base + SMEM_B_BASE + st * B_STAGE_BYTES;

#pragma unroll
        for (int s = 0; s < KC / 16; s++) {
            uint32_t a[4][4], b[4][4];
            // 1) LDSMs for this step first (critical path)
#pragma unroll
            for (int mi = 0; mi < 4; mi++) {
                int row = wm * 64 + mi * 16 + lrow;
                uint32_t off = swz((uint32_t)row * 128u +
                                   (uint32_t)(s * 16 + lkb) * 2u);
                ldmatrix_x4(a[mi], sA + off);
            }
#pragma unroll
            for (int nj = 0; nj < 4; nj++) {
                int row = wn * 64 + nj * 16 + lrow;
                uint32_t off = swz((uint32_t)row * 128u +
                                   (uint32_t)(s * 16 + lkb) * 2u);
                ldmatrix_x4(b[nj], sB + off);
            }
            // 2) 4 of the 16 next-stage cp.asyncs (drain in MMA shadow)
            if (do_load) {
#pragma unroll
                for (int i = s * 4; i < s * 4 + 4; i++) {
                    uint32_t base = (i < 8) ? wA : wB;
                    cp_async16(base + ld_soff[i], ld_gptr[i]);
                }
            }
            // 3) MMAs
#pragma unroll
            for (int mi = 0; mi < 4; mi++)
#pragma unroll
                for (int nj = 0; nj < 4; nj++) {
                    mma_16816(d[mi][2 * nj + 0], a[mi], b[nj][0], b[nj][2]);
                    mma_16816(d[mi][2 * nj + 1], a[mi], b[nj][1], b[nj][3]);
                }
        }
        CP_COMMIT();   // one group per chunk (empty in tail -> accounting holds)
        if (do_load) {
#pragma unroll
            for (int i = 0; i < 16; i++) ld_gptr[i] += KC;
        }
    }

    // epilogue: fp32 y + per-row absmax (4-lane shfl reduce + atomicMax)
    const int g = lane >> 2;
    const int tc = (lane & 3) * 2;
#pragma unroll
    for (int mi = 0; mi < 4; mi++) {
#pragma unroll
        for (int half = 0; half < 2; half++) {
            int r = m0 + wm * 64 + mi * 16 + half * 8 + g;
            float* yrow = g_y + (size_t)r * K + n0 + wn * 64;
            float mx = 0.0f;
#pragma unroll
            for (int ni = 0; ni < 8; ni++) {
                float v0 = d[mi][ni][half * 2 + 0];
                float v1 = d[mi][ni][half * 2 + 1];
                mx = fmaxf(mx, fmaxf(fabsf(v0), fabsf(v1)));
                *reinterpret_cast<float2*>(yrow + ni * 8 + tc) =
                    make_float2(v0, v1);
            }
            mx = fmaxf(mx, __shfl_xor_sync(0xFFFFFFFFu, mx, 1));
            mx = fmaxf(mx, __shfl_xor_sync(0xFFFFFFFFu, mx, 2));
            if ((lane & 3) == 0)
                atomicMax(&g_absmax[r], __float_as_uint(mx));
        }
    }
}

// ============================================================================
// quantize. mode 0 = fp32 concat [q_as_f32 | scale].
// ============================================================================
__global__ void __launch_bounds__(256) quant_kernel(void* __restrict__ d_out,
                                                    int K, long long R, int mode) {
    const int r = blockIdx.x;
    const int tid = threadIdx.x;
    const float amax = __uint_as_float(g_absmax[r]);
    const float scale = amax / 127.0f;
    const float safe = (scale == 0.0f) ? 1.0f : scale;
    const float inv = 1.0f / safe;

    const float4* yrow = reinterpret_cast<const float4*>(g_y + (size_t)r * K);
    const long long qelems = R * (long long)K;

    for (int i = tid; i < K / 4; i += 256) {
        float4 v = yrow[i];
        float vals[4] = {v.x, v.y, v.z, v.w};
        float q[4];
#pragma unroll
        for (int j = 0; j < 4; j++) {
            float t = rintf(vals[j] * inv);
            q[j] = fminf(fmaxf(t, -127.0f), 127.0f);
        }
        if (mode == 0) {
            float* out = reinterpret_cast<float*>(d_out) + (size_t)r * K + i * 4;
            *reinterpret_cast<float4*>(out) = make_float4(q[0], q[1], q[2], q[3]);
        } else {
            uint32_t p = (uint32_t)((int)q[0] & 0xFF) |
                         ((uint32_t)((int)q[1] & 0xFF) << 8) |
                         ((uint32_t)((int)q[2] & 0xFF) << 16) |
                         ((uint32_t)((int)q[3] & 0xFF) << 24);
            reinterpret_cast<uint32_t*>(
                reinterpret_cast<char*>(d_out) + (size_t)r * K)[i] = p;
        }
    }
    if (tid == 0) {
        if (mode == 0) {
            reinterpret_cast<float*>(d_out)[qelems + r] = scale;
        } else if (mode == 1) {
            float* sc = reinterpret_cast<float*>(
                reinterpret_cast<char*>(d_out) + qelems);
            sc[r] = scale;
        }
    }
}

// ============================================================================
// launcher (graph-capture clean)
// ============================================================================
static int isqrt_ll(long long v) {
    long long r = (long long)sqrt((double)v);
    while (r * r > v) r--;
    while ((r + 1) * (r + 1) <= v) r++;
    return (int)r;
}

extern "C" void kernel_launch(void* const* d_in, const int* in_sizes, int n_in,
                              void* d_out, int out_size) {
    long long s0 = in_sizes[0], s1 = (n_in > 1) ? in_sizes[1] : 0;
    const void* xv; const void* hv;
    long long numel_x, numel_h;
    if (s0 >= s1) { xv = d_in[0]; numel_x = s0; hv = d_in[1]; numel_h = s1; }
    else          { xv = d_in[1]; numel_x = s1; hv = d_in[0]; numel_h = s0; }
    const int K = isqrt_ll(numel_h);        // 2048
    const long long R = numel_x / K;        // 32768
    const long long qelems = R * (long long)K;

    int mode;
    if ((long long)out_size == qelems + R)            mode = 0;
    else if ((long long)out_size == qelems + 4LL * R) mode = 1;
    else                                              mode = 2;

    cudaFuncSetAttribute(gemm_absmax_kernel,
                         cudaFuncAttributeMaxDynamicSharedMemorySize, SMEM_TOTAL);

    zero_absmax_kernel<<<(unsigned)((R + 255) / 256), 256>>>((int)R);
    convert_x_kernel<<<(unsigned)((numel_x / 8 + 255) / 256), 256>>>(
        (const float4*)xv, numel_x / 4);
    transpose_h_kernel<<<dim3(K / 32, K / 32), dim3(32, 8)>>>((const float*)hv, K);
    gemm_absmax_kernel<<<dim3(K / NT, (unsigned)(R / MT)), THREADS, SMEM_TOTAL>>>(K);
    quant_kernel<<<(unsigned)R, 256>>>(d_out, K, R, mode);
}

// round 13
// speedup vs baseline: 1.0915x; 1.0279x over previous
#include <cuda_runtime.h>
#include <cuda_bf16.h>
#include <cstdint>
#include <cmath>

// ============================================================================
// Inputs: f32 (bf16-valued, widened by harness). K=2048, R=32768.
// Output mode 0: fp32 concat [q_as_f32 (R*K) | scale (R)].
//
// R12 crashed: swz(base)+s*32 != swz(base+s*32) (addition carries through
// XOR-swizzled bits 4..6) -> smem OOB on last stage. R13: keep RAW fragment
// offsets, swizzle at the ldmatrix site. cp.async base compression
// (soff0 + i*2048) IS linear (bits >=11) and stays.
// ============================================================================

__device__ __nv_bfloat16 g_xb[(size_t)67108864];        // 134 MB x as bf16
__device__ __nv_bfloat16 g_ht[(size_t)2048 * 2048];     // 8 MB h^T as bf16
__device__ float        g_y[(size_t)67108864];          // 268 MB fp32 y
__device__ unsigned     g_absmax[32768];                // per-row absmax bits

static constexpr int MT = 128, NT = 128, KC = 64, STAGES = 3;
static constexpr int THREADS = 128;
static constexpr int A_STAGE_BYTES = MT * KC * 2;           // 16384
static constexpr int B_STAGE_BYTES = NT * KC * 2;           // 16384
static constexpr int SMEM_B_BASE = STAGES * A_STAGE_BYTES;  // 49152
static constexpr int SMEM_TOTAL = STAGES * (A_STAGE_BYTES + B_STAGE_BYTES); // 98304

__device__ __forceinline__ uint32_t smem_u32(const void* p) {
    uint32_t a;
    asm("{ .reg .u64 t; cvta.to.shared.u64 t, %1; cvt.u32.u64 %0, t; }"
        : "=r"(a) : "l"(p));
    return a;
}
__device__ __forceinline__ uint32_t swz(uint32_t off) {
    return off ^ ((off >> 3) & 0x70u);
}
__device__ __forceinline__ void cp_async16(uint32_t s_addr, const void* g_addr) {
    asm volatile("cp.async.cg.shared.global [%0], [%1], 16;"
                 :: "r"(s_addr), "l"(g_addr) : "memory");
}
#define CP_COMMIT() asm volatile("cp.async.commit_group;" ::: "memory")
#define CP_WAIT(n)  asm volatile("cp.async.wait_group %0;" :: "n"(n) : "memory")

__device__ __forceinline__ void ldmatrix_x4(uint32_t* r, uint32_t addr) {
    asm volatile("ldmatrix.sync.aligned.m8n8.x4.shared.b16 {%0,%1,%2,%3}, [%4];"
                 : "=r"(r[0]), "=r"(r[1]), "=r"(r[2]), "=r"(r[3]) : "r"(addr));
}
__device__ __forceinline__ void mma_16816(float* d, const uint32_t* a,
                                          uint32_t b0, uint32_t b1) {
    asm volatile(
        "mma.sync.aligned.m16n8k16.row.col.f32.bf16.bf16.f32 "
        "{%0,%1,%2,%3}, {%4,%5,%6,%7}, {%8,%9}, {%0,%1,%2,%3};"
        : "+f"(d[0]), "+f"(d[1]), "+f"(d[2]), "+f"(d[3])
        : "r"(a[0]), "r"(a[1]), "r"(a[2]), "r"(a[3]), "r"(b0), "r"(b1));
}

__global__ void zero_absmax_kernel(int R) {
    int i = blockIdx.x * blockDim.x + threadIdx.x;
    if (i < R) g_absmax[i] = 0u;
}

__global__ void __launch_bounds__(256) convert_x_kernel(
    const float4* __restrict__ xf, long long n4) {
    long long i = (long long)blockIdx.x * blockDim.x + threadIdx.x;
    long long base = i * 2;
    if (base + 1 < n4) {
        float4 v0 = xf[base + 0];
        float4 v1 = xf[base + 1];
        __nv_bfloat16 o[8] = {
            __float2bfloat16(v0.x), __float2bfloat16(v0.y),
            __float2bfloat16(v0.z), __float2bfloat16(v0.w),
            __float2bfloat16(v1.x), __float2bfloat16(v1.y),
            __float2bfloat16(v1.z), __float2bfloat16(v1.w)};
        *reinterpret_cast<uint4*>(&g_xb[base * 4]) =
            *reinterpret_cast<const uint4*>(o);
    }
}

__global__ void transpose_h_kernel(const float* __restrict__ h, int K) {
    __shared__ float tile[32][33];
    int x = blockIdx.x * 32 + threadIdx.x;
    int y = blockIdx.y * 32 + threadIdx.y;
#pragma unroll
    for (int j = 0; j < 32; j += 8)
        tile[threadIdx.y + j][threadIdx.x] = h[(size_t)(y + j) * K + x];
    __syncthreads();
    int xo = blockIdx.y * 32 + threadIdx.x;
    int yo = blockIdx.x * 32 + threadIdx.y;
#pragma unroll
    for (int j = 0; j < 32; j += 8)
        g_ht[(size_t)(yo + j) * K + xo] =
            __float2bfloat16(tile[threadIdx.x][threadIdx.y + j]);
}

// ============================================================================
// GEMM + fused row absmax. 4 warps = 2(M) x 2(N), warp tile 64x64, 2 CTAs/SM,
// 3-stage pipeline, interleaved cp.async, fragment double buffering.
// ============================================================================
__global__ void __launch_bounds__(THREADS, 2) gemm_absmax_kernel(int K) {
    extern __shared__ char smem[];
    const uint32_t smem_base = smem_u32(smem);
    const int tid = threadIdx.x;
    const int wid = tid >> 5;
    const int lane = tid & 31;
    const int wm = wid >> 1;    // 0..1 (M)
    const int wn = wid & 1;     // 0..1 (N)

    const int m0 = blockIdx.y * MT;
    const int n0 = blockIdx.x * NT;

    // --- compressed cp.async bookkeeping (true linearity: i*2048 bits>=11) ---
    const int lrow0 = tid >> 3;          // 0..15
    const int lcol  = tid & 7;           // 0..7
    const uint32_t soff0 = swz((uint32_t)lrow0 * 128u + (uint32_t)lcol * 16u);
    const size_t stride16 = (size_t)16 * K;
    const __nv_bfloat16* Aptr = g_xb + (size_t)(m0 + lrow0) * K + lcol * 8;
    const __nv_bfloat16* Bptr = g_ht + (size_t)(n0 + lrow0) * K + lcol * 8;

    // --- RAW ldmatrix base offsets; swizzle applied at use site ---
    const int lrow = lane & 15;
    const int lkb  = (lane >> 4) * 8;
    uint32_t araw[4], braw[4];
#pragma unroll
    for (int mi = 0; mi < 4; mi++)
        araw[mi] = (uint32_t)(wm * 64 + mi * 16 + lrow) * 128u +
                   (uint32_t)lkb * 2u;
#pragma unroll
    for (int nj = 0; nj < 4; nj++)
        braw[nj] = (uint32_t)(wn * 64 + nj * 16 + lrow) * 128u +
                   (uint32_t)lkb * 2u;

    float d[4][8][4];
#pragma unroll
    for (int mi = 0; mi < 4; mi++)
#pragma unroll
        for (int ni = 0; ni < 8; ni++)
#pragma unroll
            for (int j = 0; j < 4; j++) d[mi][ni][j] = 0.0f;

    // prologue: stages 0..1
#pragma unroll
    for (int s = 0; s < STAGES - 1; s++) {
        uint32_t sA = smem_base + s * A_STAGE_BYTES;
        uint32_t sB = smem_base + SMEM_B_BASE + s * B_STAGE_BYTES;
#pragma unroll
        for (int i = 0; i < 8; i++)
            cp_async16(sA + soff0 + i * 2048u, Aptr + s * KC + i * stride16);
#pragma unroll
        for (int i = 0; i < 8; i++)
            cp_async16(sB + soff0 + i * 2048u, Bptr + s * KC + i * stride16);
        CP_COMMIT();
    }

    const int NCHUNK = K / KC;   // 32

    for (int kc = 0; kc < NCHUNK; kc++) {
        CP_WAIT(STAGES - 2);
        __syncthreads();   // arrived stage visible + write-target drained

        const bool do_load = (kc + STAGES - 1) < NCHUNK;
        const int wst = (kc + STAGES - 1) % STAGES;
        const uint32_t wA = smem_base + wst * A_STAGE_BYTES;
        const uint32_t wB = smem_base + SMEM_B_BASE + wst * B_STAGE_BYTES;
        const int kb_next = (kc + STAGES - 1) * KC;

        const int st = kc % STAGES;
        const uint32_t sA = smem_base + st * A_STAGE_BYTES;
        const uint32_t sB = smem_base + SMEM_B_BASE + st * B_STAGE_BYTES;

        uint32_t a[2][4][4], b[2][4][4];
        // step-0 fragments
#pragma unroll
        for (int mi = 0; mi < 4; mi++)
            ldmatrix_x4(a[0][mi], sA + swz(araw[mi]));
#pragma unroll
        for (int nj = 0; nj < 4; nj++)
            ldmatrix_x4(b[0][nj], sB + swz(braw[nj]));

#pragma unroll
        for (int s = 0; s < KC / 16; s++) {
            const int cur = s & 1;
            const int nxt = cur ^ 1;
            // prefetch step s+1 fragments (overlap with this step's MMAs)
            if (s < KC / 16 - 1) {
                uint32_t so = (uint32_t)(s + 1) * 32u;
#pragma unroll
                for (int mi = 0; mi < 4; mi++)
                    ldmatrix_x4(a[nxt][mi], sA + swz(araw[mi] + so));
#pragma unroll
                for (int nj = 0; nj < 4; nj++)
                    ldmatrix_x4(b[nxt][nj], sB + swz(braw[nj] + so));
            }
            // 4 of 16 next-stage cp.asyncs (drain in MMA shadow)
            if (do_load) {
#pragma unroll
                for (int j = 0; j < 4; j++) {
                    int i = s * 4 + j;
                    uint32_t dst = (i < 8 ? wA : wB) + soff0 + (i & 7) * 2048u;
                    const __nv_bfloat16* src =
                        (i < 8 ? Aptr : Bptr) + kb_next + (i & 7) * stride16;
                    cp_async16(dst, src);
                }
            }
            // MMAs for current step
#pragma unroll
            for (int mi = 0; mi < 4; mi++)
#pragma unroll
                for (int nj = 0; nj < 4; nj++) {
                    mma_16816(d[mi][2 * nj + 0], a[cur][mi],
                              b[cur][nj][0], b[cur][nj][2]);
                    mma_16816(d[mi][2 * nj + 1], a[cur][mi],
                              b[cur][nj][1], b[cur][nj][3]);
                }
        }
        CP_COMMIT();   // one group per chunk
    }

    // epilogue: fp32 y + per-row absmax (4-lane shfl reduce + atomicMax)
    const int g = lane >> 2;
    const int tc = (lane & 3) * 2;
#pragma unroll
    for (int mi = 0; mi < 4; mi++) {
#pragma unroll
        for (int half = 0; half < 2; half++) {
            int r = m0 + wm * 64 + mi * 16 + half * 8 + g;
            float* yrow = g_y + (size_t)r * K + n0 + wn * 64;
            float mx = 0.0f;
#pragma unroll
            for (int ni = 0; ni < 8; ni++) {
                float v0 = d[mi][ni][half * 2 + 0];
                float v1 = d[mi][ni][half * 2 + 1];
                mx = fmaxf(mx, fmaxf(fabsf(v0), fabsf(v1)));
                *reinterpret_cast<float2*>(yrow + ni * 8 + tc) =
                    make_float2(v0, v1);
            }
            mx = fmaxf(mx, __shfl_xor_sync(0xFFFFFFFFu, mx, 1));
            mx = fmaxf(mx, __shfl_xor_sync(0xFFFFFFFFu, mx, 2));
            if ((lane & 3) == 0)
                atomicMax(&g_absmax[r], __float_as_uint(mx));
        }
    }
}

// ============================================================================
// quantize. mode 0 = fp32 concat [q_as_f32 | scale].
// ============================================================================
__global__ void __launch_bounds__(256) quant_kernel(void* __restrict__ d_out,
                                                    int K, long long R, int mode) {
    const int r = blockIdx.x;
    const int tid = threadIdx.x;
    const float amax = __uint_as_float(g_absmax[r]);
    const float scale = amax / 127.0f;
    const float safe = (scale == 0.0f) ? 1.0f : scale;
    const float inv = 1.0f / safe;

    const float4* yrow = reinterpret_cast<const float4*>(g_y + (size_t)r * K);
    const long long qelems = R * (long long)K;

    for (int i = tid; i < K / 4; i += 256) {
        float4 v = yrow[i];
        float vals[4] = {v.x, v.y, v.z, v.w};
        float q[4];
#pragma unroll
        for (int j = 0; j < 4; j++) {
            float t = rintf(vals[j] * inv);
            q[j] = fminf(fmaxf(t, -127.0f), 127.0f);
        }
        if (mode == 0) {
            float* out = reinterpret_cast<float*>(d_out) + (size_t)r * K + i * 4;
            *reinterpret_cast<float4*>(out) = make_float4(q[0], q[1], q[2], q[3]);
        } else {
            uint32_t p = (uint32_t)((int)q[0] & 0xFF) |
                         ((uint32_t)((int)q[1] & 0xFF) << 8) |
                         ((uint32_t)((int)q[2] & 0xFF) << 16) |
                         ((uint32_t)((int)q[3] & 0xFF) << 24);
            reinterpret_cast<uint32_t*>(
                reinterpret_cast<char*>(d_out) + (size_t)r * K)[i] = p;
        }
    }
    if (tid == 0) {
        if (mode == 0) {
            reinterpret_cast<float*>(d_out)[qelems + r] = scale;
        } else if (mode == 1) {
            float* sc = reinterpret_cast<float*>(
                reinterpret_cast<char*>(d_out) + qelems);
            sc[r] = scale;
        }
    }
}

// ============================================================================
// launcher (graph-capture clean)
// ============================================================================
static int isqrt_ll(long long v) {
    long long r = (long long)sqrt((double)v);
    while (r * r > v) r--;
    while ((r + 1) * (r + 1) <= v) r++;
    return (int)r;
}

extern "C" void kernel_launch(void* const* d_in, const int* in_sizes, int n_in,
                              void* d_out, int out_size) {
    long long s0 = in_sizes[0], s1 = (n_in > 1) ? in_sizes[1] : 0;
    const void* xv; const void* hv;
    long long numel_x, numel_h;
    if (s0 >= s1) { xv = d_in[0]; numel_x = s0; hv = d_in[1]; numel_h = s1; }
    else          { xv = d_in[1]; numel_x = s1; hv = d_in[0]; numel_h = s0; }
    const int K = isqrt_ll(numel_h);        // 2048
    const long long R = numel_x / K;        // 32768
    const long long qelems = R * (long long)K;

    int mode;
    if ((long long)out_size == qelems + R)            mode = 0;
    else if ((long long)out_size == qelems + 4LL * R) mode = 1;
    else                                              mode = 2;

    cudaFuncSetAttribute(gemm_absmax_kernel,
                         cudaFuncAttributeMaxDynamicSharedMemorySize, SMEM_TOTAL);

    zero_absmax_kernel<<<(unsigned)((R + 255) / 256), 256>>>((int)R);
    convert_x_kernel<<<(unsigned)((numel_x / 8 + 255) / 256), 256>>>(
        (const float4*)xv, numel_x / 4);
    transpose_h_kernel<<<dim3(K / 32, K / 32), dim3(32, 8)>>>((const float*)hv, K);
    gemm_absmax_kernel<<<dim3(K / NT, (unsigned)(R / MT)), THREADS, SMEM_TOTAL>>>(K);
    quant_kernel<<<(unsigned)R, 256>>>(d_out, K, R, mode);
}

// round 14
// speedup vs baseline: 1.1572x; 1.0603x over previous
#include <cuda_runtime.h>
#include <cuda_bf16.h>
#include <cstdint>
#include <cmath>

// ============================================================================
// Inputs: f32 (bf16-valued, widened by harness). K=2048, R=32768.
// Output mode 0: fp32 concat [q_as_f32 (R*K) | scale (R)].
//
// R13: 686us GEMM + ~85us separate quant pass (536MB traffic). R14: fused
// cross-CTA epilogue — the 16 N-tile CTAs of each m-slab rendezvous on a
// per-slab counter after atomicMax; then each quantizes its register tile
// and writes q directly to d_out. g_y eliminated in mode 0.
// ============================================================================

__device__ __nv_bfloat16 g_xb[(size_t)67108864];        // 134 MB x as bf16
__device__ __nv_bfloat16 g_ht[(size_t)2048 * 2048];     // 8 MB h^T as bf16
__device__ float        g_y[(size_t)67108864];          // fallback (mode!=0)
__device__ unsigned     g_absmax[32768];                // per-row absmax bits
__device__ unsigned     g_cnt[1024];                    // per-m-slab arrival ctr

static constexpr int MT = 128, NT = 128, KC = 64, STAGES = 3;
static constexpr int THREADS = 128;
static constexpr int A_STAGE_BYTES = MT * KC * 2;           // 16384
static constexpr int B_STAGE_BYTES = NT * KC * 2;           // 16384
static constexpr int SMEM_B_BASE = STAGES * A_STAGE_BYTES;  // 49152
static constexpr int SMEM_TOTAL = STAGES * (A_STAGE_BYTES + B_STAGE_BYTES); // 98304

__device__ __forceinline__ uint32_t smem_u32(const void* p) {
    uint32_t a;
    asm("{ .reg .u64 t; cvta.to.shared.u64 t, %1; cvt.u32.u64 %0, t; }"
        : "=r"(a) : "l"(p));
    return a;
}
__device__ __forceinline__ uint32_t swz(uint32_t off) {
    return off ^ ((off >> 3) & 0x70u);
}
__device__ __forceinline__ void cp_async16(uint32_t s_addr, const void* g_addr) {
    asm volatile("cp.async.cg.shared.global [%0], [%1], 16;"
                 :: "r"(s_addr), "l"(g_addr) : "memory");
}
#define CP_COMMIT() asm volatile("cp.async.commit_group;" ::: "memory")
#define CP_WAIT(n)  asm volatile("cp.async.wait_group %0;" :: "n"(n) : "memory")

__device__ __forceinline__ void ldmatrix_x4(uint32_t* r, uint32_t addr) {
    asm volatile("ldmatrix.sync.aligned.m8n8.x4.shared.b16 {%0,%1,%2,%3}, [%4];"
                 : "=r"(r[0]), "=r"(r[1]), "=r"(r[2]), "=r"(r[3]) : "r"(addr));
}
__device__ __forceinline__ void mma_16816(float* d, const uint32_t* a,
                                          uint32_t b0, uint32_t b1) {
    asm volatile(
        "mma.sync.aligned.m16n8k16.row.col.f32.bf16.bf16.f32 "
        "{%0,%1,%2,%3}, {%4,%5,%6,%7}, {%8,%9}, {%0,%1,%2,%3};"
        : "+f"(d[0]), "+f"(d[1]), "+f"(d[2]), "+f"(d[3])
        : "r"(a[0]), "r"(a[1]), "r"(a[2]), "r"(a[3]), "r"(b0), "r"(b1));
}

__global__ void zero_meta_kernel(int R) {
    int i = blockIdx.x * blockDim.x + threadIdx.x;
    if (i < R) g_absmax[i] = 0u;
    if (i < 1024) g_cnt[i] = 0u;
}

__global__ void __launch_bounds__(256) convert_x_kernel(
    const float4* __restrict__ xf, long long n4) {
    long long i = (long long)blockIdx.x * blockDim.x + threadIdx.x;
    long long base = i * 2;
    if (base + 1 < n4) {
        float4 v0 = xf[base + 0];
        float4 v1 = xf[base + 1];
        __nv_bfloat16 o[8] = {
            __float2bfloat16(v0.x), __float2bfloat16(v0.y),
            __float2bfloat16(v0.z), __float2bfloat16(v0.w),
            __float2bfloat16(v1.x), __float2bfloat16(v1.y),
            __float2bfloat16(v1.z), __float2bfloat16(v1.w)};
        *reinterpret_cast<uint4*>(&g_xb[base * 4]) =
            *reinterpret_cast<const uint4*>(o);
    }
}

__global__ void transpose_h_kernel(const float* __restrict__ h, int K) {
    __shared__ float tile[32][33];
    int x = blockIdx.x * 32 + threadIdx.x;
    int y = blockIdx.y * 32 + threadIdx.y;
#pragma unroll
    for (int j = 0; j < 32; j += 8)
        tile[threadIdx.y + j][threadIdx.x] = h[(size_t)(y + j) * K + x];
    __syncthreads();
    int xo = blockIdx.y * 32 + threadIdx.x;
    int yo = blockIdx.x * 32 + threadIdx.y;
#pragma unroll
    for (int j = 0; j < 32; j += 8)
        g_ht[(size_t)(yo + j) * K + xo] =
            __float2bfloat16(tile[threadIdx.x][threadIdx.y + j]);
}

// ============================================================================
// GEMM + fused absmax + fused cross-CTA quantization epilogue.
// 4 warps = 2(M) x 2(N), warp tile 64x64, 2 CTAs/SM, 3-stage pipeline.
// ============================================================================
__global__ void __launch_bounds__(THREADS, 2) gemm_fused_kernel(
    void* __restrict__ d_out, int K, long long R, int mode) {
    extern __shared__ char smem[];
    const uint32_t smem_base = smem_u32(smem);
    const int tid = threadIdx.x;
    const int wid = tid >> 5;
    const int lane = tid & 31;
    const int wm = wid >> 1;
    const int wn = wid & 1;

    const int m0 = blockIdx.y * MT;
    const int n0 = blockIdx.x * NT;

    const int lrow0 = tid >> 3;
    const int lcol  = tid & 7;
    const uint32_t soff0 = swz((uint32_t)lrow0 * 128u + (uint32_t)lcol * 16u);
    const size_t stride16 = (size_t)16 * K;
    const __nv_bfloat16* Aptr = g_xb + (size_t)(m0 + lrow0) * K + lcol * 8;
    const __nv_bfloat16* Bptr = g_ht + (size_t)(n0 + lrow0) * K + lcol * 8;

    const int lrow = lane & 15;
    const int lkb  = (lane >> 4) * 8;
    uint32_t araw[4], braw[4];
#pragma unroll
    for (int mi = 0; mi < 4; mi++)
        araw[mi] = (uint32_t)(wm * 64 + mi * 16 + lrow) * 128u +
                   (uint32_t)lkb * 2u;
#pragma unroll
    for (int nj = 0; nj < 4; nj++)
        braw[nj] = (uint32_t)(wn * 64 + nj * 16 + lrow) * 128u +
                   (uint32_t)lkb * 2u;

    float d[4][8][4];
#pragma unroll
    for (int mi = 0; mi < 4; mi++)
#pragma unroll
        for (int ni = 0; ni < 8; ni++)
#pragma unroll
            for (int j = 0; j < 4; j++) d[mi][ni][j] = 0.0f;

#pragma unroll
    for (int s = 0; s < STAGES - 1; s++) {
        uint32_t sA = smem_base + s * A_STAGE_BYTES;
        uint32_t sB = smem_base + SMEM_B_BASE + s * B_STAGE_BYTES;
#pragma unroll
        for (int i = 0; i < 8; i++)
            cp_async16(sA + soff0 + i * 2048u, Aptr + s * KC + i * stride16);
#pragma unroll
        for (int i = 0; i < 8; i++)
            cp_async16(sB + soff0 + i * 2048u, Bptr + s * KC + i * stride16);
        CP_COMMIT();
    }

    const int NCHUNK = K / KC;

    for (int kc = 0; kc < NCHUNK; kc++) {
        CP_WAIT(STAGES - 2);
        __syncthreads();

        const bool do_load = (kc + STAGES - 1) < NCHUNK;
        const int wst = (kc + STAGES - 1) % STAGES;
        const uint32_t wA = smem_base + wst * A_STAGE_BYTES;
        const uint32_t wB = smem_base + SMEM_B_BASE + wst * B_STAGE_BYTES;
        const int kb_next = (kc + STAGES - 1) * KC;

        const int st = kc % STAGES;
        const uint32_t sA = smem_base + st * A_STAGE_BYTES;
        const uint32_t sB = smem_base + SMEM_B_BASE + st * B_STAGE_BYTES;

        uint32_t a[2][4][4], b[2][4][4];
#pragma unroll
        for (int mi = 0; mi < 4; mi++)
            ldmatrix_x4(a[0][mi], sA + swz(araw[mi]));
#pragma unroll
        for (int nj = 0; nj < 4; nj++)
            ldmatrix_x4(b[0][nj], sB + swz(braw[nj]));

#pragma unroll
        for (int s = 0; s < KC / 16; s++) {
            const int cur = s & 1;
            const int nxt = cur ^ 1;
            if (s < KC / 16 - 1) {
                uint32_t so = (uint32_t)(s + 1) * 32u;
#pragma unroll
                for (int mi = 0; mi < 4; mi++)
                    ldmatrix_x4(a[nxt][mi], sA + swz(araw[mi] + so));
#pragma unroll
                for (int nj = 0; nj < 4; nj++)
                    ldmatrix_x4(b[nxt][nj], sB + swz(braw[nj] + so));
            }
            if (do_load) {
#pragma unroll
                for (int j = 0; j < 4; j++) {
                    int i = s * 4 + j;
                    uint32_t dst = (i < 8 ? wA : wB) + soff0 + (i & 7) * 2048u;
                    const __nv_bfloat16* src =
                        (i < 8 ? Aptr : Bptr) + kb_next + (i & 7) * stride16;
                    cp_async16(dst, src);
                }
            }
#pragma unroll
            for (int mi = 0; mi < 4; mi++)
#pragma unroll
                for (int nj = 0; nj < 4; nj++) {
                    mma_16816(d[mi][2 * nj + 0], a[cur][mi],
                              b[cur][nj][0], b[cur][nj][2]);
                    mma_16816(d[mi][2 * nj + 1], a[cur][mi],
                              b[cur][nj][1], b[cur][nj][3]);
                }
        }
        CP_COMMIT();
    }

    // ---- epilogue phase 1: row absmax (register tile) + atomicMax ----
    const int g = lane >> 2;
    const int tc = (lane & 3) * 2;
#pragma unroll
    for (int mi = 0; mi < 4; mi++) {
#pragma unroll
        for (int half = 0; half < 2; half++) {
            int r = m0 + wm * 64 + mi * 16 + half * 8 + g;
            float mx = 0.0f;
#pragma unroll
            for (int ni = 0; ni < 8; ni++) {
                mx = fmaxf(mx, fmaxf(fabsf(d[mi][ni][half * 2 + 0]),
                                     fabsf(d[mi][ni][half * 2 + 1])));
            }
            mx = fmaxf(mx, __shfl_xor_sync(0xFFFFFFFFu, mx, 1));
            mx = fmaxf(mx, __shfl_xor_sync(0xFFFFFFFFu, mx, 2));
            if ((lane & 3) == 0)
                atomicMax(&g_absmax[r], __float_as_uint(mx));
        }
    }

    if (mode != 0) {
        // fallback: write y, separate quant kernel handles output
#pragma unroll
        for (int mi = 0; mi < 4; mi++)
#pragma unroll
            for (int half = 0; half < 2; half++) {
                int r = m0 + wm * 64 + mi * 16 + half * 8 + g;
                float* yrow = g_y + (size_t)r * K + n0 + wn * 64;
#pragma unroll
                for (int ni = 0; ni < 8; ni++)
                    *reinterpret_cast<float2*>(yrow + ni * 8 + tc) =
                        make_float2(d[mi][ni][half * 2 + 0],
                                    d[mi][ni][half * 2 + 1]);
            }
        return;
    }

    // ---- epilogue phase 2: slab rendezvous ----
    __syncthreads();                       // all warps' atomicMax issued
    if (tid == 0) {
        __threadfence();                   // maxes visible before arrival
        atomicAdd(&g_cnt[blockIdx.y], 1u);
        unsigned target = gridDim.x;
        unsigned v;
        do {
            asm volatile("ld.acquire.gpu.global.u32 %0, [%1];"
                         : "=r"(v) : "l"(&g_cnt[blockIdx.y]));
        } while (v < target);
    }
    __syncthreads();                       // absmax now final + visible

    // ---- epilogue phase 3: quantize register tile -> d_out (fp32 concat) ----
    float* outq = reinterpret_cast<float*>(d_out);
    const long long qelems = R * (long long)K;
#pragma unroll
    for (int mi = 0; mi < 4; mi++) {
#pragma unroll
        for (int half = 0; half < 2; half++) {
            int r = m0 + wm * 64 + mi * 16 + half * 8 + g;
            unsigned ab;
            asm volatile("ld.global.cg.u32 %0, [%1];"
                         : "=r"(ab) : "l"(&g_absmax[r]));
            const float amax = __uint_as_float(ab);
            const float scale = amax / 127.0f;
            const float inv = (scale == 0.0f) ? 1.0f : (1.0f / scale);
            float* qrow = outq + (size_t)r * K + n0 + wn * 64;
#pragma unroll
            for (int ni = 0; ni < 8; ni++) {
                float q0 = rintf(d[mi][ni][half * 2 + 0] * inv);
                float q1 = rintf(d[mi][ni][half * 2 + 1] * inv);
                q0 = fminf(fmaxf(q0, -127.0f), 127.0f);
                q1 = fminf(fmaxf(q1, -127.0f), 127.0f);
                *reinterpret_cast<float2*>(qrow + ni * 8 + tc) =
                    make_float2(q0, q1);
            }
        }
    }
    // scales: CTA with n0==0 writes its slab's 128 scales
    if (blockIdx.x == 0) {
        int r = m0 + tid;   // 128 threads, 128 rows
        unsigned ab;
        asm volatile("ld.global.cg.u32 %0, [%1];"
                     : "=r"(ab) : "l"(&g_absmax[r]));
        outq[qelems + r] = __uint_as_float(ab) / 127.0f;
    }
}

// ============================================================================
// quantize fallback for modes 1/2 (not used for the confirmed instance)
// ============================================================================
__global__ void __launch_bounds__(256) quant_kernel(void* __restrict__ d_out,
                                                    int K, long long R, int mode) {
    const int r = blockIdx.x;
    const int tid = threadIdx.x;
    const float amax = __uint_as_float(g_absmax[r]);
    const float scale = amax / 127.0f;
    const float safe = (scale == 0.0f) ? 1.0f : scale;
    const float inv = 1.0f / safe;

    const float4* yrow = reinterpret_cast<const float4*>(g_y + (size_t)r * K);
    const long long qelems = R * (long long)K;

    for (int i = tid; i < K / 4; i += 256) {
        float4 v = yrow[i];
        float vals[4] = {v.x, v.y, v.z, v.w};
        int q[4];
#pragma unroll
        for (int j = 0; j < 4; j++) {
            float t = rintf(vals[j] * inv);
            q[j] = (int)fminf(fmaxf(t, -127.0f), 127.0f);
        }
        uint32_t p = (uint32_t)(q[0] & 0xFF) | ((uint32_t)(q[1] & 0xFF) << 8) |
                     ((uint32_t)(q[2] & 0xFF) << 16) | ((uint32_t)(q[3] & 0xFF) << 24);
        reinterpret_cast<uint32_t*>(
            reinterpret_cast<char*>(d_out) + (size_t)r * K)[i] = p;
    }
    if (tid == 0 && mode == 1) {
        float* sc = reinterpret_cast<float*>(
            reinterpret_cast<char*>(d_out) + qelems);
        sc[r] = scale;
    }
}

// ============================================================================
// launcher (graph-capture clean)
// ============================================================================
static int isqrt_ll(long long v) {
    long long r = (long long)sqrt((double)v);
    while (r * r > v) r--;
    while ((r + 1) * (r + 1) <= v) r++;
    return (int)r;
}

extern "C" void kernel_launch(void* const* d_in, const int* in_sizes, int n_in,
                              void* d_out, int out_size) {
    long long s0 = in_sizes[0], s1 = (n_in > 1) ? in_sizes[1] : 0;
    const void* xv; const void* hv;
    long long numel_x, numel_h;
    if (s0 >= s1) { xv = d_in[0]; numel_x = s0; hv = d_in[1]; numel_h = s1; }
    else          { xv = d_in[1]; numel_x = s1; hv = d_in[0]; numel_h = s0; }
    const int K = isqrt_ll(numel_h);        // 2048
    const long long R = numel_x / K;        // 32768
    const long long qelems = R * (long long)K;

    int mode;
    if ((long long)out_size == qelems + R)            mode = 0;
    else if ((long long)out_size == qelems + 4LL * R) mode = 1;
    else                                              mode = 2;

    cudaFuncSetAttribute(gemm_fused_kernel,
                         cudaFuncAttributeMaxDynamicSharedMemorySize, SMEM_TOTAL);

    zero_meta_kernel<<<(unsigned)((R + 255) / 256), 256>>>((int)R);
    convert_x_kernel<<<(unsigned)((numel_x / 8 + 255) / 256), 256>>>(
        (const float4*)xv, numel_x / 4);
    transpose_h_kernel<<<dim3(K / 32, K / 32), dim3(32, 8)>>>((const float*)hv, K);
    gemm_fused_kernel<<<dim3(K / NT, (unsigned)(R / MT)), THREADS, SMEM_TOTAL>>>(
        d_out, K, R, mode);
    if (mode != 0)
        quant_kernel<<<(unsigned)R, 256>>>(d_out, K, R, mode);
}